// round 5
// baseline (speedup 1.0000x reference)
#include <cuda_runtime.h>
#include <cstdint>

// Palette packed keys: (r<<16)|(g<<8)|b  -> class id == index
// 0: 0x000000  1: 0x800000  2: 0x804080  3: 0xC000C0
// 4: 0x008000  5: 0x808000  6: 0x404000  7: 0x400080

__device__ __forceinline__ float classify(int r, int g, int b) {
    unsigned key = ((unsigned)r << 16) | ((unsigned)g << 8) | (unsigned)b;
    int c = 0;
    c += (key == 0x800000u) ? 1 : 0;
    c += (key == 0x804080u) ? 2 : 0;
    c += (key == 0xC000C0u) ? 3 : 0;
    c += (key == 0x008000u) ? 4 : 0;
    c += (key == 0x808000u) ? 5 : 0;
    c += (key == 0x404000u) ? 6 : 0;
    c += (key == 0x400080u) ? 7 : 0;
    return (float)c;  // unmatched (incl. key 0) -> 0
}

__device__ __forceinline__ float4 classify4(int4 r, int4 g, int4 b) {
    float4 o;
    o.x = classify(r.x, g.x, b.x);
    o.y = classify(r.y, g.y, b.y);
    o.z = classify(r.z, g.z, b.z);
    o.w = classify(r.w, g.w, b.w);
    return o;
}

// 8 pixels/thread, 6 independent warp-coalesced 16B loads.
// Quad 0 at i, quad 1 at i + stride (stride = total threads) so every
// LDG.128 is lane-contiguous (16 lines per warp).
__global__ void __launch_bounds__(256)
uavid_vec8c_f32_kernel(const int4* __restrict__ rp,
                       const int4* __restrict__ gp,
                       const int4* __restrict__ bp,
                       float4* __restrict__ out,
                       int n4, int stride) {
    int i = blockIdx.x * blockDim.x + threadIdx.x;
    int j = i + stride;
    if (j < n4) {
        int4 r0 = rp[i];
        int4 g0 = gp[i];
        int4 b0 = bp[i];
        int4 r1 = rp[j];
        int4 g1 = gp[j];
        int4 b1 = bp[j];
        out[i] = classify4(r0, g0, b0);
        out[j] = classify4(r1, g1, b1);
    } else if (i < n4) {
        int4 r0 = rp[i];
        int4 g0 = gp[i];
        int4 b0 = bp[i];
        out[i] = classify4(r0, g0, b0);
    }
}

__global__ void uavid_tail_f32_kernel(const int* __restrict__ rp,
                                      const int* __restrict__ gp,
                                      const int* __restrict__ bp,
                                      float* __restrict__ out,
                                      int start, int hw) {
    int i = start + blockIdx.x * blockDim.x + threadIdx.x;
    if (i >= hw) return;
    out[i] = classify(rp[i], gp[i], bp[i]);
}

extern "C" void kernel_launch(void* const* d_in, const int* in_sizes, int n_in,
                              void* d_out, int out_size) {
    const int* t = (const int*)d_in[0];
    int n  = in_sizes[0];     // 3 * H * W
    int hw = n / 3;           // H * W
    const int* rp = t;
    const int* gp = t + hw;
    const int* bp = t + 2 * hw;

    int n4  = hw >> 2;        // vectorized pixel-quads
    int rem = hw & 3;

    if (n4 > 0) {
        int threads = 256;
        int blocks  = (n4 + 2 * threads - 1) / (2 * threads);
        int stride  = blocks * threads;   // total threads in grid
        uavid_vec8c_f32_kernel<<<blocks, threads>>>(
            (const int4*)rp, (const int4*)gp, (const int4*)bp,
            (float4*)d_out, n4, stride);
    }
    if (rem > 0) {
        uavid_tail_f32_kernel<<<1, 256>>>(rp, gp, bp,
                                          (float*)d_out, n4 << 2, hw);
    }
}

// round 6
// speedup vs baseline: 1.0592x; 1.0592x over previous
#include <cuda_runtime.h>
#include <cstdint>

// Palette packed keys: (r<<16)|(g<<8)|b  -> class id == index
// 0: 0x000000  1: 0x800000  2: 0x804080  3: 0xC000C0
// 4: 0x008000  5: 0x808000  6: 0x404000  7: 0x400080

__device__ __forceinline__ float classify(int r, int g, int b) {
    unsigned key = ((unsigned)r << 16) | ((unsigned)g << 8) | (unsigned)b;
    int c = 0;
    c += (key == 0x800000u) ? 1 : 0;
    c += (key == 0x804080u) ? 2 : 0;
    c += (key == 0xC000C0u) ? 3 : 0;
    c += (key == 0x008000u) ? 4 : 0;
    c += (key == 0x808000u) ? 5 : 0;
    c += (key == 0x404000u) ? 6 : 0;
    c += (key == 0x400080u) ? 7 : 0;
    return (float)c;  // unmatched (incl. key 0) -> 0
}

__global__ void __launch_bounds__(256)
uavid_vec4_cs_kernel(const int4* __restrict__ rp,
                     const int4* __restrict__ gp,
                     const int4* __restrict__ bp,
                     float4* __restrict__ out,
                     int n4) {
    int i = blockIdx.x * blockDim.x + threadIdx.x;
    if (i >= n4) return;
    int4 r = __ldcs(&rp[i]);
    int4 g = __ldcs(&gp[i]);
    int4 b = __ldcs(&bp[i]);
    float4 o;
    o.x = classify(r.x, g.x, b.x);
    o.y = classify(r.y, g.y, b.y);
    o.z = classify(r.z, g.z, b.z);
    o.w = classify(r.w, g.w, b.w);
    __stcs(&out[i], o);
}

__global__ void uavid_tail_f32_kernel(const int* __restrict__ rp,
                                      const int* __restrict__ gp,
                                      const int* __restrict__ bp,
                                      float* __restrict__ out,
                                      int start, int hw) {
    int i = start + blockIdx.x * blockDim.x + threadIdx.x;
    if (i >= hw) return;
    out[i] = classify(rp[i], gp[i], bp[i]);
}

extern "C" void kernel_launch(void* const* d_in, const int* in_sizes, int n_in,
                              void* d_out, int out_size) {
    const int* t = (const int*)d_in[0];
    int n  = in_sizes[0];     // 3 * H * W
    int hw = n / 3;           // H * W
    const int* rp = t;
    const int* gp = t + hw;
    const int* bp = t + 2 * hw;

    int n4  = hw >> 2;        // vectorized pixel-quads
    int rem = hw & 3;

    if (n4 > 0) {
        int threads = 256;
        int blocks  = (n4 + threads - 1) / threads;
        uavid_vec4_cs_kernel<<<blocks, threads>>>(
            (const int4*)rp, (const int4*)gp, (const int4*)bp,
            (float4*)d_out, n4);
    }
    if (rem > 0) {
        uavid_tail_f32_kernel<<<1, 256>>>(rp, gp, bp,
                                          (float*)d_out, n4 << 2, hw);
    }
}

// round 7
// speedup vs baseline: 1.0695x; 1.0097x over previous
#include <cuda_runtime.h>
#include <cstdint>

// Palette packed keys: (r<<16)|(g<<8)|b  -> class id == index
// 0: 0x000000  1: 0x800000  2: 0x804080  3: 0xC000C0
// 4: 0x008000  5: 0x808000  6: 0x404000  7: 0x400080

__device__ __forceinline__ float classify(int r, int g, int b) {
    unsigned key = ((unsigned)r << 16) | ((unsigned)g << 8) | (unsigned)b;
    int c = 0;
    c += (key == 0x800000u) ? 1 : 0;
    c += (key == 0x804080u) ? 2 : 0;
    c += (key == 0xC000C0u) ? 3 : 0;
    c += (key == 0x008000u) ? 4 : 0;
    c += (key == 0x808000u) ? 5 : 0;
    c += (key == 0x404000u) ? 6 : 0;
    c += (key == 0x400080u) ? 7 : 0;
    return (float)c;  // unmatched (incl. key 0) -> 0
}

// Persistent single-wave grid-stride kernel: 4 px/thread/iter via int4/float4.
__global__ void __launch_bounds__(256)
uavid_persist_kernel(const int4* __restrict__ rp,
                     const int4* __restrict__ gp,
                     const int4* __restrict__ bp,
                     float4* __restrict__ out,
                     int n4) {
    int stride = gridDim.x * blockDim.x;
    for (int i = blockIdx.x * blockDim.x + threadIdx.x; i < n4; i += stride) {
        int4 r = __ldcs(&rp[i]);
        int4 g = __ldcs(&gp[i]);
        int4 b = __ldcs(&bp[i]);
        float4 o;
        o.x = classify(r.x, g.x, b.x);
        o.y = classify(r.y, g.y, b.y);
        o.z = classify(r.z, g.z, b.z);
        o.w = classify(r.w, g.w, b.w);
        __stcs(&out[i], o);
    }
}

__global__ void uavid_tail_f32_kernel(const int* __restrict__ rp,
                                      const int* __restrict__ gp,
                                      const int* __restrict__ bp,
                                      float* __restrict__ out,
                                      int start, int hw) {
    int i = start + blockIdx.x * blockDim.x + threadIdx.x;
    if (i >= hw) return;
    out[i] = classify(rp[i], gp[i], bp[i]);
}

extern "C" void kernel_launch(void* const* d_in, const int* in_sizes, int n_in,
                              void* d_out, int out_size) {
    const int* t = (const int*)d_in[0];
    int n  = in_sizes[0];     // 3 * H * W
    int hw = n / 3;           // H * W
    const int* rp = t;
    const int* gp = t + hw;
    const int* bp = t + 2 * hw;

    int n4  = hw >> 2;        // vectorized pixel-quads
    int rem = hw & 3;

    if (n4 > 0) {
        int threads = 256;
        // One wave: 148 SMs x 8 CTAs (256 thr -> 8 warps/CTA, 64 warps/SM cap)
        int blocks = 148 * 8;
        int max_blocks = (n4 + threads - 1) / threads;
        if (blocks > max_blocks) blocks = max_blocks;
        uavid_persist_kernel<<<blocks, threads>>>(
            (const int4*)rp, (const int4*)gp, (const int4*)bp,
            (float4*)d_out, n4);
    }
    if (rem > 0) {
        uavid_tail_f32_kernel<<<1, 256>>>(rp, gp, bp,
                                          (float*)d_out, n4 << 2, hw);
    }
}